// round 12
// baseline (speedup 1.0000x reference)
#include <cuda_runtime.h>

// Problem dims
#define NCC 4
#define BSZ 16
#define NTT 32
#define SSLICE (BSZ*64*64*12)   // 786432 floats per (BS,H,W,OC) slab

// Persistent device state
__device__ __align__(16) float g_slabs[5][SSLICE];
__device__ __align__(16) float g_class_c[NCC*SSLICE];
__device__ __align__(16) float g_genh[2][SSLICE];
__device__ __align__(16) float g_genc[SSLICE];

// Reordered weights: [k][ic][third][gate][4]; third th owns oc channels
// gate*12 + th*4 .. +3 of every gate.
__device__ __align__(16) float g_wg[9*60*48];
__device__ __align__(16) float g_wc[9*36*48];

// Slab schedule + grid barrier counter (zeroed per replay)
__device__ int g_rslab[NTT*NCC];
__device__ int g_wslab[NTT];
__device__ unsigned int g_barc;

__device__ __forceinline__ float hsig(float x) {
    return fminf(fmaxf(x + 3.0f, 0.0f), 6.0f) * (1.0f/6.0f);
}

typedef unsigned long long ull;

__device__ __forceinline__ ull pack2(float x) {
    ull r;
    unsigned int xi = __float_as_uint(x);
    asm("mov.b64 %0, {%1, %1};" : "=l"(r) : "r"(xi));
    return r;
}
__device__ __forceinline__ void ffma2(ull& d, ull a, ull b) {
    asm("fma.rn.f32x2 %0, %1, %2, %0;" : "+l"(d) : "l"(a), "l"(b));
}
__device__ __forceinline__ float2 unpack2(ull v) {
    float2 r;
    asm("mov.b64 {%0, %1}, %2;" : "=f"(r.x), "=f"(r.y) : "l"(v));
    return r;
}

// L2-coherent float4 load (cross-CTA state inside the persistent kernel —
// L1 is not coherent across SMs and is no longer flushed per step).
__device__ __forceinline__ float4 ldcg4(const float* p) {
    float4 v;
    asm volatile("ld.global.cg.v4.f32 {%0,%1,%2,%3}, [%4];"
                 : "=f"(v.x), "=f"(v.y), "=f"(v.z), "=f"(v.w) : "l"(p));
    return v;
}

// Grid-wide barrier: monotonic counter, all 128 CTAs resident (1 CTA/SM
// enforced by 198KB smem), so spinning is deadlock-free.
__device__ __forceinline__ void grid_barrier(unsigned target) {
    __syncthreads();
    if (threadIdx.x == 0) {
        __threadfence();
        atomicAdd(&g_barc, 1u);
        while (atomicAdd(&g_barc, 0u) < target) __nanosleep(128);
    }
    __syncthreads();
}

// --------------------------------------------------------------------------
// 12-channel conv tap, 16-oc third per thread. Channel stride 48 floats =
// 12 ulonglong2; this thread's 16 floats contiguous (4 u2).
// xb channel-major: channel icc at xb[icc*660], next row +66.
// --------------------------------------------------------------------------
__device__ __forceinline__ void conv12t(const float* __restrict__ sWk,
                                        const float* __restrict__ xb,
                                        ull* __restrict__ acc0,
                                        ull* __restrict__ acc1)
{
    const ulonglong2* wp = (const ulonglong2*)sWk;
    #pragma unroll 2
    for (int icc = 0; icc < 12; ++icc) {
        ull xp0 = pack2(xb[icc*660]);
        ull xp1 = pack2(xb[icc*660 + 66]);
        const ulonglong2* w = wp + icc*12;
        #pragma unroll
        for (int p = 0; p < 4; ++p) {
            ulonglong2 ww = w[p];
            ffma2(acc0[2*p],   xp0, ww.x);
            ffma2(acc0[2*p+1], xp0, ww.y);
            ffma2(acc1[2*p],   xp1, ww.x);
            ffma2(acc1[2*p+1], xp1, ww.y);
        }
    }
}

// --------------------------------------------------------------------------
__global__ void zero_kernel(float* __restrict__ out, const int* __restrict__ cids)
{
    const int tid    = blockIdx.x * blockDim.x + threadIdx.x;
    const int stride = gridDim.x * blockDim.x;
    for (int i = tid; i < 5*SSLICE; i += stride)
        (&g_slabs[0][0])[i] = 0.0f;
    for (int i = tid; i < NCC*SSLICE; i += stride)
        g_class_c[i] = 0.0f;
    for (int i = tid; i < SSLICE; i += stride) {
        g_genh[0][i] = 0.0f;
        g_genc[i]    = 0.0f;
        out[i]       = 0.0f;
    }
    if (tid == 0) {
        g_barc = 0u;
        int slab[NCC] = {0, 1, 2, 3};
        int spare = 4;
        for (int t = 0; t < NTT; ++t) {
            int cid = cids[t];
            #pragma unroll
            for (int c = 0; c < NCC; ++c) g_rslab[t*4 + c] = slab[c];
            g_wslab[t] = spare;
            int old = slab[cid];
            slab[cid] = spare;
            spare = old;
        }
    }
}

// --------------------------------------------------------------------------
// One-time weight reorder into [k][ic][third][gate][4] layout.
// --------------------------------------------------------------------------
__global__ void reorder_kernel(const float* __restrict__ Wxg, const float* __restrict__ Whg,
                               const float* __restrict__ Wxc, const float* __restrict__ Whc)
{
    const int tid    = blockIdx.x * blockDim.x + threadIdx.x;
    const int stride = gridDim.x * blockDim.x;
    const float4* wx4 = (const float4*)Wxg;
    const float4* wh4 = (const float4*)Whg;
    for (int e = tid; e < 9*60*12; e += stride) {
        int th   = e % 3;
        int gate = (e/3) & 3;
        int ic   = (e/12) % 60;
        int k    = e / 720;
        float4 v = (ic < 48) ? wx4[(k*48 + ic)*12 + gate*3 + th]
                             : wh4[(k*12 + (ic - 48))*12 + gate*3 + th];
        ((float4*)g_wg)[((k*60 + ic)*3 + th)*4 + gate] = v;
    }
    const float4* cx4 = (const float4*)Wxc;
    const float4* ch4 = (const float4*)Whc;
    for (int e = tid; e < 9*36*12; e += stride) {
        int th   = e % 3;
        int gate = (e/3) & 3;
        int ic   = (e/12) % 36;
        int k    = e / 432;
        float4 v = (ic < 24) ? cx4[(k*24 + ic)*12 + gate*3 + th]
                             : ch4[(k*12 + (ic - 24))*12 + gate*3 + th];
        ((float4*)g_wc)[((k*36 + ic)*3 + th)*4 + gate] = v;
    }
}

// ==========================================================================
// Persistent fused kernel: 128 CTAs (grid 8x16), 768 threads, all 32 steps.
// Per step: gen phase -> grid barrier -> cls phase -> grid barrier.
// Weights staged into smem ONCE. Cross-CTA state via cg loads + barriers.
// Smem: sWg 104KB | sWc 62KB | sIn 31KB | biases -> 198KB (1 CTA/SM).
// ==========================================================================
#define OFF_WC 25920
#define OFF_IN (25920 + 15552)
#define OFF_BG (OFF_IN + 7920)
#define OFF_BC (OFF_BG + 48)
#define P_SMEM_FLOATS (OFF_BC + 48)
#define P_SMEM_BYTES (P_SMEM_FLOATS*4)

__global__ __launch_bounds__(768, 1)
void fused_kernel(const float* __restrict__ x, const int* __restrict__ cids,
                  const float* __restrict__ bg, const float* __restrict__ bc,
                  float* __restrict__ out)
{
    extern __shared__ float smem[];
    float* sWg = smem;
    float* sWc = smem + OFF_WC;
    float* sIn = smem + OFF_IN;
    float* sBg = smem + OFF_BG;
    float* sBc = smem + OFF_BC;

    const int tid = threadIdx.x;
    const int tx  = tid & 63;
    const int rg  = (tid >> 6) & 3;
    const int th  = tid >> 8;          // 0..2
    const int b   = blockIdx.y;
    const int y0  = blockIdx.x * 8;

    // Stage both weight sets + biases once per replay
    for (int e = tid; e < 6480; e += 768) ((float4*)sWg)[e] = ((const float4*)g_wg)[e];
    for (int e = tid; e < 3888; e += 768) ((float4*)sWc)[e] = ((const float4*)g_wc)[e];
    if (tid < 12)                   ((float4*)sBg)[tid]      = ((const float4*)bg)[tid];
    else if (tid >= 16 && tid < 28) ((float4*)sBc)[tid - 16] = ((const float4*)bc)[tid - 16];

    // Staging coordinates (3 slots/thread, invariant across chunks/steps)
    int ppx[3], pq[3], ppidx[3];
    bool pok[3], pinr[3];
    #pragma unroll
    for (int i = 0; i < 3; ++i) {
        int e  = tid + i*768;
        bool inr = e < 1980;
        int px = e/3, q = e - px*3;
        int yy = px/66, xx = px - yy*66;
        int gy = y0 + yy - 1, gx = xx - 1;
        bool inb = inr && (unsigned)gy < 64u && (unsigned)gx < 64u;
        ppx[i] = px; pq[i] = q;
        ppidx[i] = inb ? ((b*64 + gy)*64 + gx) : 0;
        pok[i] = inb; pinr[i] = inr;
    }

    unsigned bar_target = 0;

    #pragma unroll 1
    for (int t = 0; t < NTT; ++t) {
        const int par = t & 1;
        const float* genh_in  = g_genh[par];
        float*       genh_out = g_genh[par ^ 1];
        const float* bankp    = g_slabs[g_rslab[t*4 + (b >> 2)]];

        // ================= GEN phase =================
        {
            ull acc0[8], acc1[8];
            #pragma unroll
            for (int p = 0; p < 8; ++p) { acc0[p] = 0ull; acc1[p] = 0ull; }

            float4 pf[3];
            #pragma unroll
            for (int i = 0; i < 3; ++i)
                pf[i] = pok[i] ? ldcg4(bankp + (size_t)(ppidx[i] & 16383)*48 + pq[i]*4)
                               : make_float4(0.f, 0.f, 0.f, 0.f);

            #pragma unroll 1
            for (int ch = 0; ch < 5; ++ch) {
                __syncthreads();
                #pragma unroll
                for (int i = 0; i < 3; ++i) {
                    if (pinr[i]) {
                        int base = pq[i]*4*660 + ppx[i];
                        sIn[base]        = pf[i].x;
                        sIn[base +  660] = pf[i].y;
                        sIn[base + 1320] = pf[i].z;
                        sIn[base + 1980] = pf[i].w;
                    }
                }
                __syncthreads();
                if (ch < 4) {
                    #pragma unroll
                    for (int i = 0; i < 3; ++i) {
                        if (!pok[i]) { pf[i] = make_float4(0.f,0.f,0.f,0.f); continue; }
                        pf[i] = (ch < 3)
                            ? ldcg4(bankp + (size_t)(ppidx[i] & 16383)*48 + (ch+1)*12 + pq[i]*4)
                            : ldcg4(genh_in + (size_t)ppidx[i]*12 + pq[i]*4);
                    }
                }

                #pragma unroll 1
                for (int k = 0; k < 9; ++k) {
                    const int ky = k / 3;
                    const int kx = k - ky*3;
                    conv12t(sWg + ((k*60 + ch*12)*3 + th)*16,
                            sIn + (rg*2 + ky)*66 + tx + kx,
                            acc0, acc1);
                }
            }

            #pragma unroll
            for (int r = 0; r < 2; ++r) {
                ull* accr = r ? acc1 : acc0;
                float z[16];
                #pragma unroll
                for (int p = 0; p < 8; ++p) {
                    float2 v = unpack2(accr[p]);
                    z[2*p] = v.x; z[2*p+1] = v.y;
                }
                const int gy  = y0 + rg*2 + r;
                const int idx = ((b*64 + gy)*64 + tx)*12 + th*4;
                float4 c4 = *(const float4*)(g_genc + idx);   // CTA-private
                float4 h4;
                float* cf = (float*)&c4;
                float* hf = (float*)&h4;
                #pragma unroll
                for (int j = 0; j < 4; ++j) {
                    float zi = z[j]      + sBg[th*4 + j];
                    float zf = z[4 + j]  + sBg[12 + th*4 + j];
                    float zg = z[8 + j]  + sBg[24 + th*4 + j];
                    float zo = z[12 + j] + sBg[36 + th*4 + j];
                    float fi = hsig(zi), ff = hsig(zf), fo = hsig(zo);
                    float cn = ff * cf[j] + fi * tanhf(zg);
                    cf[j] = cn;
                    hf[j] = fo * tanhf(cn);
                }
                *(float4*)(g_genc + idx)   = c4;
                *(float4*)(genh_out + idx) = h4;
            }
        }

        bar_target += 128;
        grid_barrier(bar_target);

        // ================= CLS phase =================
        {
            const int cid = __ldg(cids + t);
            const float* chh   = g_slabs[g_rslab[t*4 + cid]];
            float*       hnew  = g_slabs[g_wslab[t]];
            const float* frame = x + (size_t)(b*NTT + t)*4096*12;

            ull acc0[8], acc1[8];
            #pragma unroll
            for (int p = 0; p < 8; ++p) { acc0[p] = 0ull; acc1[p] = 0ull; }

            float4 pf[3];
            #pragma unroll
            for (int i = 0; i < 3; ++i)
                pf[i] = pok[i] ? ldcg4(frame + (size_t)(ppidx[i] & 4095)*12 + pq[i]*4)
                               : make_float4(0.f, 0.f, 0.f, 0.f);

            #pragma unroll 1
            for (int ch = 0; ch < 3; ++ch) {
                __syncthreads();
                #pragma unroll
                for (int i = 0; i < 3; ++i) {
                    if (pinr[i]) {
                        int base = pq[i]*4*660 + ppx[i];
                        sIn[base]        = pf[i].x;
                        sIn[base +  660] = pf[i].y;
                        sIn[base + 1320] = pf[i].z;
                        sIn[base + 1980] = pf[i].w;
                    }
                }
                __syncthreads();
                if (ch < 2) {
                    #pragma unroll
                    for (int i = 0; i < 3; ++i) {
                        if (!pok[i]) { pf[i] = make_float4(0.f,0.f,0.f,0.f); continue; }
                        pf[i] = (ch == 0)
                            ? ldcg4(genh_out + (size_t)ppidx[i]*12 + pq[i]*4)
                            : ldcg4(chh + (size_t)ppidx[i]*12 + pq[i]*4);
                    }
                }

                #pragma unroll 1
                for (int k = 0; k < 9; ++k) {
                    const int ky = k / 3;
                    const int kx = k - ky*3;
                    conv12t(sWc + ((k*36 + ch*12)*3 + th)*16,
                            sIn + (rg*2 + ky)*66 + tx + kx,
                            acc0, acc1);
                }
            }

            float* chc = g_class_c + (size_t)cid * SSLICE;

            #pragma unroll
            for (int r = 0; r < 2; ++r) {
                ull* accr = r ? acc1 : acc0;
                float z[16];
                #pragma unroll
                for (int p = 0; p < 8; ++p) {
                    float2 v = unpack2(accr[p]);
                    z[2*p] = v.x; z[2*p+1] = v.y;
                }
                const int gy  = y0 + rg*2 + r;
                const int idx = ((b*64 + gy)*64 + tx)*12 + th*4;
                float4 c4 = *(const float4*)(chc + idx);   // CTA-private
                float4 o4 = *(const float4*)(out + idx);   // CTA-private
                float4 h4;
                float* cf = (float*)&c4;
                float* hf = (float*)&h4;
                float* of = (float*)&o4;
                #pragma unroll
                for (int j = 0; j < 4; ++j) {
                    float zi = z[j]      + sBc[th*4 + j];
                    float zf = z[4 + j]  + sBc[12 + th*4 + j];
                    float zg = z[8 + j]  + sBc[24 + th*4 + j];
                    float zo = z[12 + j] + sBc[36 + th*4 + j];
                    float fi = hsig(zi), ff = hsig(zf), fo = hsig(zo);
                    float cn = ff * cf[j] + fi * tanhf(zg);
                    float hn = fo * tanhf(cn);
                    cf[j] = cn;
                    hf[j] = hn;
                    of[j] += hn;
                }
                *(float4*)(chc + idx)  = c4;
                *(float4*)(hnew + idx) = h4;
                *(float4*)(out + idx)  = o4;
            }
        }

        bar_target += 128;
        grid_barrier(bar_target);
    }
}

// --------------------------------------------------------------------------
extern "C" void kernel_launch(void* const* d_in, const int* in_sizes, int n_in,
                              void* d_out, int out_size)
{
    const float* x    = (const float*)d_in[0];
    const int*   cids = (const int*)d_in[1];
    const float* Wxg  = (const float*)d_in[2];
    const float* Whg  = (const float*)d_in[3];
    const float* bg   = (const float*)d_in[4];
    const float* Wxc  = (const float*)d_in[5];
    const float* Whc  = (const float*)d_in[6];
    const float* bc   = (const float*)d_in[7];
    float* out = (float*)d_out;

    cudaFuncSetAttribute(fused_kernel, cudaFuncAttributeMaxDynamicSharedMemorySize,
                         P_SMEM_BYTES);

    zero_kernel<<<1024, 256>>>(out, cids);
    reorder_kernel<<<64, 256>>>(Wxg, Whg, Wxc, Whc);
    fused_kernel<<<dim3(8, 16), 768, P_SMEM_BYTES>>>(x, cids, bg, bc, out);
}